// round 16
// baseline (speedup 1.0000x reference)
#include <cuda_runtime.h>
#include <math.h>

// Problem constants
#define B_ 64
#define S_ 1024
#define I_ 300
#define H_ 1024
#define O_ 100
#define T_ 1023        // S-1 timesteps actually computed
#define KT 32          // K tile (4 x k8 MMA steps)
#define NTH 128        // threads per block (4 warps)
#define NBLK 130       // 64 L1 + 64 L2 + 2 OUT (all resident: 130 < 148 SMs)

// Persistent state (device globals: no allocation allowed)
__device__ float g_h1[2][B_ * H_];
__device__ float g_h2[2][B_ * H_];
__device__ float g_c1[B_ * H_];
__device__ float g_c2[B_ * H_];
__device__ unsigned g_bar_count;
__device__ volatile unsigned g_bar_gen;

__device__ __forceinline__ float sigf(float x) { return 1.0f / (1.0f + expf(-x)); }

// ---------- tf32 helpers ----------
__device__ __forceinline__ unsigned cvt_tf32(float f) {
    unsigned u;
    asm("cvt.rna.tf32.f32 %0, %1;" : "=r"(u) : "f"(f));
    return u;
}
// 3xTF32 split: v = hi + lo (both tf32-representable); error ~2^-22 relative.
__device__ __forceinline__ float2 split_tf32(float v) {
    unsigned h = cvt_tf32(v);
    float hf = __uint_as_float(h);
    float lf = __uint_as_float(cvt_tf32(v - hf));
    return make_float2(hf, lf);
}
__device__ __forceinline__ void mma8(float d[4],
                                     unsigned a0, unsigned a1, unsigned a2, unsigned a3,
                                     unsigned b0, unsigned b1) {
    asm volatile(
        "mma.sync.aligned.m16n8k8.row.col.f32.tf32.tf32.f32 "
        "{%0,%1,%2,%3}, {%4,%5,%6,%7}, {%8,%9}, {%0,%1,%2,%3};"
        : "+f"(d[0]), "+f"(d[1]), "+f"(d[2]), "+f"(d[3])
        : "r"(a0), "r"(a1), "r"(a2), "r"(a3), "r"(b0), "r"(b1));
}

// Load 16 consecutive floats with tail guard. LDCG=true bypasses L1
// (recurrent state written by other SMs; no per-launch L1 flush here).
template <bool LDCG>
__device__ __forceinline__ void load16(float r[16], const float* __restrict__ p,
                                       int k0, int K) {
    if (k0 + 16 <= K) {
        #pragma unroll
        for (int j = 0; j < 16; j += 4) {
            float4 v = LDCG ? __ldcg(reinterpret_cast<const float4*>(p + k0 + j))
                            : *reinterpret_cast<const float4*>(p + k0 + j);
            r[j] = v.x; r[j + 1] = v.y; r[j + 2] = v.z; r[j + 3] = v.w;
        }
    } else {
        #pragma unroll
        for (int j = 0; j < 16; ++j)
            r[j] = (k0 + j < K) ? (LDCG ? __ldcg(p + k0 + j) : p[k0 + j]) : 0.0f;
    }
}

// ACC[64 rows][64 cols] += U[64 x K] * W[cols]^T via 3xTF32 m16n8k8 MMA.
// 4 warps; warp tile 32x32 (wm=w&1 row half, wn=w>>1 col half):
//   2 m16-tiles x 4 n8-tiles, 3 mma each per k8-step.
// SMEM staging stores pre-split (hi,lo) float2 pairs:
//   uS: rows physically interleaved (r, r+8 adjacent -> one LDS.128 per A pair)
//   wS: columns rotated by 2*(k&3) (conflict-lean B loads)
template <bool UCG>
__device__ __forceinline__ void gemm_mma(
    float acc[2][4][4],
    float2 (*uS)[64], float2 (*wS)[64],
    const float* __restrict__ U, long long ldu,
    const float* __restrict__ W, long long ldw, int wrow, int K)
{
    const int tid  = threadIdx.x;
    const int lane = tid & 31;
    const int w    = tid >> 5;
    const int wm   = w & 1, wn = w >> 1;
    const int tig  = lane & 3, gid = lane >> 2;
    const int lb   = tid & 63;             // staging row/col 0..63
    const int lk0  = (tid >> 6) << 4;      // 0 or 16
    // physical interleave: rows r and r+8 of a 16-group land adjacent
    const int up   = (lb & 48) | ((lb & 7) << 1) | ((lb >> 3) & 1);

    const float* Up = U + (long long)lb * ldu;
    const float* Wp = W + (long long)wrow * ldw;

    float ur[16], wr[16];
    load16<UCG>(ur, Up, lk0, K);
    load16<false>(wr, Wp, lk0, K);

    const int ntiles = (K + KT - 1) / KT;
    for (int t = 0; t < ntiles; ++t) {
        __syncthreads();   // previous tile's readers are done
        #pragma unroll
        for (int j = 0; j < 16; ++j) {
            int k = lk0 + j;
            uS[k][up] = split_tf32(ur[j]);
            wS[k][(lb + 2 * (k & 3)) & 63] = split_tf32(wr[j]);
        }
        __syncthreads();   // tiles published
        if (t + 1 < ntiles) {
            int k0n = (t + 1) * KT + lk0;
            load16<UCG>(ur, Up, k0n, K);     // LDG overlaps MMA below
            load16<false>(wr, Wp, k0n, K);
        }
        #pragma unroll
        for (int k0 = 0; k0 < KT; k0 += 8) {
            // A fragments (hi/lo) for the 2 m16-tiles: one LDS.128 per k-half
            unsigned ah[2][4], al[2][4];
            #pragma unroll
            for (int mt = 0; mt < 2; ++mt) {
                int col = wm * 32 + mt * 16 + 2 * gid;   // even -> 16B aligned
                float4 v0 = *reinterpret_cast<const float4*>(&uS[k0 + tig][col]);
                float4 v1 = *reinterpret_cast<const float4*>(&uS[k0 + tig + 4][col]);
                ah[mt][0] = __float_as_uint(v0.x); al[mt][0] = __float_as_uint(v0.y);
                ah[mt][1] = __float_as_uint(v0.z); al[mt][1] = __float_as_uint(v0.w);
                ah[mt][2] = __float_as_uint(v1.x); al[mt][2] = __float_as_uint(v1.y);
                ah[mt][3] = __float_as_uint(v1.z); al[mt][3] = __float_as_uint(v1.w);
            }
            #pragma unroll
            for (int nt = 0; nt < 4; ++nt) {
                // rotation 2*((k0+tig)&3) == 2*tig for both k halves (k0, +4 mult. of 4)
                int colp = (wn * 32 + nt * 8 + gid + 2 * tig) & 63;
                float2 b0 = wS[k0 + tig][colp];
                float2 b1 = wS[k0 + tig + 4][colp];
                unsigned b0h = __float_as_uint(b0.x), b0l = __float_as_uint(b0.y);
                unsigned b1h = __float_as_uint(b1.x), b1l = __float_as_uint(b1.y);
                #pragma unroll
                for (int mt = 0; mt < 2; ++mt) {
                    mma8(acc[mt][nt], ah[mt][0], ah[mt][1], ah[mt][2], ah[mt][3], b0h, b1h);
                    mma8(acc[mt][nt], ah[mt][0], ah[mt][1], ah[mt][2], ah[mt][3], b0l, b1l);
                    mma8(acc[mt][nt], al[mt][0], al[mt][1], al[mt][2], al[mt][3], b0h, b1h);
                }
            }
        }
    }
}

// LSTM epilogue. D-fragment cols 2q,2q+1: even lanes hold (i,f), odd lanes (g,o)
// of the same unit; one shfl_xor(1) completes each lane's gate set for one row.
__device__ __forceinline__ void lstm_epi(
    float acc[2][4][4],
    const float* __restrict__ bih, const float* __restrict__ bhh,
    float* __restrict__ cst, float* __restrict__ hout, int u0)
{
    const int tid = threadIdx.x;
    const int lane = tid & 31, w = tid >> 5, wm = w & 1, wn = w >> 1;
    const int gid = lane >> 2, q = lane & 3;
    #pragma unroll
    for (int nt = 0; nt < 4; ++nt) {
        int cA = wn * 32 + nt * 8 + 2 * q;         // even col: gate cA&3 in {0,2}
        int rA = (cA & 3) * H_ + u0 + (cA >> 2);
        int rB = ((cA + 1) & 3) * H_ + u0 + (cA >> 2);
        float bA = bih[rA] + bhh[rA];
        float bB = bih[rB] + bhh[rB];
        int unit = u0 + (cA >> 2);
        #pragma unroll
        for (int mt = 0; mt < 2; ++mt) {
            float d0 = acc[mt][nt][0] + bA;        // (row gid,   col cA)
            float d1 = acc[mt][nt][1] + bB;        // (row gid,   col cA+1)
            float d2 = acc[mt][nt][2] + bA;        // (row gid+8, col cA)
            float d3 = acc[mt][nt][3] + bB;        // (row gid+8, col cA+1)
            float o0 = __shfl_xor_sync(0xffffffffu, d0, 1);
            float o1 = __shfl_xor_sync(0xffffffffu, d1, 1);
            float o2 = __shfl_xor_sync(0xffffffffu, d2, 1);
            float o3 = __shfl_xor_sync(0xffffffffu, d3, 1);
            int row; float pi, pf, pg, po;
            if ((q & 1) == 0) {  // this lane holds (i,f); partner supplies (g,o)
                row = wm * 32 + mt * 16 + gid;
                pi = d0; pf = d1; pg = o0; po = o1;
            } else {             // this lane holds (g,o); partner supplies (i,f)
                row = wm * 32 + mt * 16 + gid + 8;
                pi = o2; pf = o3; pg = d2; po = d3;
            }
            float iv = sigf(pi), fv = sigf(pf), gv = tanhf(pg), ov = sigf(po);
            long long idx = (long long)row * H_ + unit;
            float cn = fv * cst[idx] + iv * gv;
            cst[idx] = cn;
            hout[idx] = ov * tanhf(cn);
        }
    }
}

// Zero recurrent state, barrier, and out[:, 0, :]
__global__ void init_kernel(float* __restrict__ out) {
    int idx = blockIdx.x * blockDim.x + threadIdx.x;
    if (idx == 0) { g_bar_count = 0; g_bar_gen = 0; }
    if (idx < 2 * B_ * H_) {
        ((float*)g_h1)[idx] = 0.0f;
        ((float*)g_h2)[idx] = 0.0f;
    }
    if (idx < B_ * H_) {
        g_c1[idx] = 0.0f;
        g_c2[idx] = 0.0f;
    }
    if (idx < B_ * O_) {
        int b = idx / O_, o = idx % O_;
        out[(long long)b * S_ * O_ + o] = 0.0f;  // t = 0 row is all zeros
    }
}

// Persistent kernel. One pipeline interval k per iteration (k = 0..T_+1):
//   blocks   0..63 : layer-1 -> h1(k)            (active k <= T_-1)
//   blocks  64..127: layer-2 -> h2(k-1)          (active 1 <= k <= T_)
//   blocks 128..129: output  -> out at t = k-1   (active k >= 2)
// Buffers: h1(j) lives in g_h1[j&1]; h2(j) lives in g_h2[j&1].
__global__ void __launch_bounds__(NTH, 1) lstm_persistent(
    const float* __restrict__ x,
    const float* __restrict__ Wih1, const float* __restrict__ Whh1,
    const float* __restrict__ bih1, const float* __restrict__ bhh1,
    const float* __restrict__ Wih2, const float* __restrict__ Whh2,
    const float* __restrict__ bih2, const float* __restrict__ bhh2,
    const float* __restrict__ Wout, const float* __restrict__ bout,
    float* __restrict__ out)
{
    __shared__ float2 uS[KT][64];   // (hi,lo) pairs, rows interleaved
    __shared__ float2 wS[KT][64];   // (hi,lo) pairs, cols rotated by 2*(k&3)

    const int blk = blockIdx.x;
    const int tid = threadIdx.x;
    const int lb  = tid & 63;

    float acc[2][4][4];

    for (int k = 0; k <= T_ + 1; ++k) {
        if (blk < 64) {
            // ---- Layer 1: h1(k), c1 from h1(k-1), c1, x[:, k+1, :] ----
            if (k < T_) {
                const int u0 = blk * 16;
                const float* h1prev = g_h1[(k + 1) & 1];   // h1(k-1)
                float* h1out = g_h1[k & 1];                // h1(k)
                #pragma unroll
                for (int a = 0; a < 2; ++a)
                    #pragma unroll
                    for (int b = 0; b < 4; ++b)
                        #pragma unroll
                        for (int c = 0; c < 4; ++c) acc[a][b][c] = 0.0f;
                const int wrow = (lb & 3) * H_ + u0 + (lb >> 2);
                gemm_mma<false>(acc, uS, wS, x + (long long)(k + 1) * I_,
                                (long long)S_ * I_, Wih1, I_, wrow, I_);
                gemm_mma<true>(acc, uS, wS, h1prev, H_, Whh1, H_, wrow, H_);
                lstm_epi(acc, bih1, bhh1, g_c1, h1out, u0);
            }
        } else if (blk < 128) {
            // ---- Layer 2: h2(k-1), c2 from h1(k-1), h2(k-2), c2 ----
            if (k >= 1 && k <= T_) {
                const int u0 = (blk - 64) * 16;
                const float* h1prev = g_h1[(k + 1) & 1];   // h1(k-1)
                const float* h2prev = g_h2[k & 1];         // h2(k-2)
                float* h2out = g_h2[(k + 1) & 1];          // h2(k-1)
                #pragma unroll
                for (int a = 0; a < 2; ++a)
                    #pragma unroll
                    for (int b = 0; b < 4; ++b)
                        #pragma unroll
                        for (int c = 0; c < 4; ++c) acc[a][b][c] = 0.0f;
                const int wrow = (lb & 3) * H_ + u0 + (lb >> 2);
                gemm_mma<true>(acc, uS, wS, h1prev, H_, Wih2, H_, wrow, H_);
                gemm_mma<true>(acc, uS, wS, h2prev, H_, Whh2, H_, wrow, H_);
                lstm_epi(acc, bih2, bhh2, g_c2, h2out, u0);
            }
        } else {
            // ---- Output projection: out(t'=k-2) = h2(k-2) @ Wout^T + bout ----
            if (k >= 2) {
                const int cb = (blk - 128) * 64;
                const float* h2src = g_h2[k & 1];          // h2(k-2)
                #pragma unroll
                for (int a = 0; a < 2; ++a)
                    #pragma unroll
                    for (int b = 0; b < 4; ++b)
                        #pragma unroll
                        for (int c = 0; c < 4; ++c) acc[a][b][c] = 0.0f;
                int wr_ = cb + lb;
                if (wr_ >= O_) wr_ = O_ - 1;               // clamp; results discarded
                gemm_mma<true>(acc, uS, wS, h2src, H_, Wout, H_, wr_, H_);

                const int lane = tid & 31, w = tid >> 5, wm = w & 1, wn = w >> 1;
                const int gid = lane >> 2, q = lane & 3;
                const int tout = k - 1;                    // out index t'+1
                #pragma unroll
                for (int nt = 0; nt < 4; ++nt) {
                    int c0 = cb + wn * 32 + nt * 8 + 2 * q;
                    #pragma unroll
                    for (int mt = 0; mt < 2; ++mt) {
                        int r0 = wm * 32 + mt * 16 + gid;
                        if (c0 < O_) {
                            float bv = bout[c0];
                            out[((long long)r0 * S_ + tout) * O_ + c0] =
                                acc[mt][nt][0] + bv;
                            out[((long long)(r0 + 8) * S_ + tout) * O_ + c0] =
                                acc[mt][nt][2] + bv;
                        }
                        if (c0 + 1 < O_) {
                            float bv = bout[c0 + 1];
                            out[((long long)r0 * S_ + tout) * O_ + c0 + 1] =
                                acc[mt][nt][1] + bv;
                            out[((long long)(r0 + 8) * S_ + tout) * O_ + c0 + 1] =
                                acc[mt][nt][3] + bv;
                        }
                    }
                }
            }
        }

        // ---- Grid barrier (all 130 CTAs resident: 130 < 148 SMs) ----
        __threadfence();     // release: this CTA's state writes visible at L2
        __syncthreads();
        if (tid == 0) {
            unsigned gen = g_bar_gen;
            unsigned t = atomicAdd(&g_bar_count, 1u);
            if (t == NBLK - 1) {
                g_bar_count = 0;
                __threadfence();
                g_bar_gen = gen + 1;
            } else {
                while (g_bar_gen == gen) { }
            }
        }
        __syncthreads();
        __threadfence();     // acquire: subsequent reads see other CTAs' writes
    }
}

extern "C" void kernel_launch(void* const* d_in, const int* in_sizes, int n_in,
                              void* d_out, int out_size) {
    const float* x    = (const float*)d_in[0];
    const float* Wih1 = (const float*)d_in[1];
    const float* Whh1 = (const float*)d_in[2];
    const float* bih1 = (const float*)d_in[3];
    const float* bhh1 = (const float*)d_in[4];
    const float* Wih2 = (const float*)d_in[5];
    const float* Whh2 = (const float*)d_in[6];
    const float* bih2 = (const float*)d_in[7];
    const float* bhh2 = (const float*)d_in[8];
    const float* Wout = (const float*)d_in[9];
    const float* bout = (const float*)d_in[10];
    float* out = (float*)d_out;

    init_kernel<<<(2 * B_ * H_ + 255) / 256, 256>>>(out);
    lstm_persistent<<<NBLK, NTH>>>(x, Wih1, Whh1, bih1, bhh1,
                                   Wih2, Whh2, bih2, bhh2, Wout, bout, out);
}

// round 17
// speedup vs baseline: 1.4215x; 1.4215x over previous
#include <cuda_runtime.h>
#include <math.h>

// Problem constants
#define B_ 64
#define S_ 1024
#define I_ 300
#define H_ 1024
#define O_ 100
#define T_ 1023        // S-1 timesteps actually computed
#define KT 32          // K tile (4 x k8 MMA steps)
#define NTH 128        // threads per block (4 warps)
#define NBLK 130       // 64 L1 + 64 L2 + 2 OUT (all resident: 130 < 148 SMs)

#define TILE_F2   (KT * 64)        // float2 elements per staged tile (2048)
#define TILE_B    (TILE_F2 * 8)    // 16 KB
#define SMEM_BYTES (4 * TILE_B)    // uS[2] + wS[2] = 64 KB (dynamic)

// ---------------- persistent device state (no allocation allowed) ----------
// h states stored PRE-SPLIT (tf32 hi/lo) and transposed: [unit][interleaved row]
__device__ __align__(16) float2 g_h1s[2][H_][B_];
__device__ __align__(16) float2 g_h2s[2][H_][B_];
__device__ float g_c1[B_ * H_];
__device__ float g_c2[B_ * H_];
__device__ unsigned g_bar_count;
__device__ volatile unsigned g_bar_gen;

// Weights pre-split into the exact SMEM fragment-tile layout:
//   g_wXX[cta][k][(col + 2*(k&3)) & 63] = split_tf32( W[wrow(cta,col)][k] )
__device__ __align__(16) float2 g_w1h[64][H_][64];   // Whh1
__device__ __align__(16) float2 g_w2i[64][H_][64];   // Wih2
__device__ __align__(16) float2 g_w2h[64][H_][64];   // Whh2
__device__ __align__(16) float2 g_wo [2][H_][64];    // Wout (zero-padded cols >= O_)

__device__ __forceinline__ float sigf(float x) { return 1.0f / (1.0f + expf(-x)); }

// ---------- tf32 helpers ----------
__device__ __forceinline__ unsigned cvt_tf32(float f) {
    unsigned u;
    asm("cvt.rna.tf32.f32 %0, %1;" : "=r"(u) : "f"(f));
    return u;
}
// 3xTF32 split: v = hi + lo (both tf32-representable); error ~2^-22 relative.
__device__ __forceinline__ float2 split_tf32(float v) {
    unsigned h = cvt_tf32(v);
    float hf = __uint_as_float(h);
    float lf = __uint_as_float(cvt_tf32(v - hf));
    return make_float2(hf, lf);
}
__device__ __forceinline__ void mma8(float d[4],
                                     unsigned a0, unsigned a1, unsigned a2, unsigned a3,
                                     unsigned b0, unsigned b1) {
    asm volatile(
        "mma.sync.aligned.m16n8k8.row.col.f32.tf32.tf32.f32 "
        "{%0,%1,%2,%3}, {%4,%5,%6,%7}, {%8,%9}, {%0,%1,%2,%3};"
        : "+f"(d[0]), "+f"(d[1]), "+f"(d[2]), "+f"(d[3])
        : "r"(a0), "r"(a1), "r"(a2), "r"(a3), "r"(b0), "r"(b1));
}

// physical row interleave: rows r and r+8 of each 16-group land adjacent
__device__ __forceinline__ int il_row(int r) {
    return (r & 48) | ((r & 7) << 1) | ((r >> 3) & 1);
}

// ---------- cp.async helpers ----------
__device__ __forceinline__ unsigned smem_u32(const void* p) {
    return (unsigned)__cvta_generic_to_shared(p);
}
__device__ __forceinline__ void cpa16(unsigned s, const float2* g) {
    asm volatile("cp.async.cg.shared.global [%0], [%1], 16;" :: "r"(s), "l"(g));
}
#define CPA_COMMIT() asm volatile("cp.async.commit_group;")
#define CPA_WAIT(n)  asm volatile("cp.async.wait_group %0;" :: "n"(n))

// ---------- MMA on one staged tile (fragment mapping identical to R16) ----------
__device__ __forceinline__ void mma_tile(float acc[2][4][4],
                                         const float2 (*uT)[64],
                                         const float2 (*wT)[64],
                                         int wm, int wn, int tig, int gid) {
    #pragma unroll
    for (int k0 = 0; k0 < KT; k0 += 8) {
        unsigned ah[2][4], al[2][4];
        #pragma unroll
        for (int mt = 0; mt < 2; ++mt) {
            int col = wm * 32 + mt * 16 + 2 * gid;   // even -> 16B aligned
            float4 v0 = *reinterpret_cast<const float4*>(&uT[k0 + tig][col]);
            float4 v1 = *reinterpret_cast<const float4*>(&uT[k0 + tig + 4][col]);
            ah[mt][0] = __float_as_uint(v0.x); al[mt][0] = __float_as_uint(v0.y);
            ah[mt][1] = __float_as_uint(v0.z); al[mt][1] = __float_as_uint(v0.w);
            ah[mt][2] = __float_as_uint(v1.x); al[mt][2] = __float_as_uint(v1.y);
            ah[mt][3] = __float_as_uint(v1.z); al[mt][3] = __float_as_uint(v1.w);
        }
        #pragma unroll
        for (int nt = 0; nt < 4; ++nt) {
            // rotation 2*((k0+tig)&3) == 2*tig for both k halves
            int colp = (wn * 32 + nt * 8 + gid + 2 * tig) & 63;
            float2 b0 = wT[k0 + tig][colp];
            float2 b1 = wT[k0 + tig + 4][colp];
            unsigned b0h = __float_as_uint(b0.x), b0l = __float_as_uint(b0.y);
            unsigned b1h = __float_as_uint(b1.x), b1l = __float_as_uint(b1.y);
            #pragma unroll
            for (int mt = 0; mt < 2; ++mt) {
                mma8(acc[mt][nt], ah[mt][0], ah[mt][1], ah[mt][2], ah[mt][3], b0h, b1h);
                mma8(acc[mt][nt], ah[mt][0], ah[mt][1], ah[mt][2], ah[mt][3], b0l, b1l);
                mma8(acc[mt][nt], al[mt][0], al[mt][1], al[mt][2], al[mt][3], b0h, b1h);
            }
        }
    }
}

// ---------- pre-split GEMM: pure cp.async copy staging, double-buffered ----------
__device__ __forceinline__ void gemm_ps(float acc[2][4][4],
                                        float2 (*uS)[KT][64], float2 (*wS)[KT][64],
                                        const float2* __restrict__ Us,
                                        const float2* __restrict__ Ws,
                                        int ntiles) {
    const int tid = threadIdx.x;
    const int lane = tid & 31, w = tid >> 5;
    const int wm = w & 1, wn = w >> 1;
    const int tig = lane & 3, gid = lane >> 2;
    const int toff = tid * 2;   // float2 units; 16B per thread per pass

    unsigned su0 = smem_u32(&uS[0][0][0]), su1 = smem_u32(&uS[1][0][0]);
    unsigned sw0 = smem_u32(&wS[0][0][0]), sw1 = smem_u32(&wS[1][0][0]);

    __syncthreads();   // prior users of the staging buffers are done

    // prologue: issue tile 0 into stage 0
    #pragma unroll
    for (int p = 0; p < 8; ++p) {
        int idx = toff + p * 256;
        cpa16(su0 + idx * 8, Us + idx);
        cpa16(sw0 + idx * 8, Ws + idx);
    }
    CPA_COMMIT();

    for (int t = 0; t < ntiles; ++t) {
        int st = t & 1;
        if (t + 1 < ntiles) {
            unsigned du = (st == 0) ? su1 : su0;
            unsigned dw = (st == 0) ? sw1 : sw0;
            const float2* un = Us + (t + 1) * TILE_F2;
            const float2* wn_ = Ws + (t + 1) * TILE_F2;
            #pragma unroll
            for (int p = 0; p < 8; ++p) {
                int idx = toff + p * 256;
                cpa16(du + idx * 8, un + idx);
                cpa16(dw + idx * 8, wn_ + idx);
            }
            CPA_COMMIT();
            CPA_WAIT(1);           // tile t complete (t+1 may stay in flight)
        } else {
            CPA_WAIT(0);
        }
        __syncthreads();
        mma_tile(acc, uS[st], wS[st], wm, wn, tig, gid);
        __syncthreads();           // readers done before stage is overwritten
    }
}

// ---------- x GEMM: fp32 sources, split at staging (L1 path only; has slack) ----
__device__ __forceinline__ void load16g(float r[16], const float* __restrict__ p,
                                        int k0, int K) {
    if (k0 + 16 <= K) {
        #pragma unroll
        for (int j = 0; j < 16; j += 4) {
            float4 v = *reinterpret_cast<const float4*>(p + k0 + j);
            r[j] = v.x; r[j + 1] = v.y; r[j + 2] = v.z; r[j + 3] = v.w;
        }
    } else {
        #pragma unroll
        for (int j = 0; j < 16; ++j)
            r[j] = (k0 + j < K) ? p[k0 + j] : 0.0f;
    }
}

__device__ __forceinline__ void gemm_x(float acc[2][4][4],
                                       float2 (*uT)[64], float2 (*wT)[64],
                                       const float* __restrict__ U, long long ldu,
                                       const float* __restrict__ W, long long ldw,
                                       int wrow, int K) {
    const int tid = threadIdx.x;
    const int lane = tid & 31, w = tid >> 5;
    const int wm = w & 1, wn = w >> 1;
    const int tig = lane & 3, gid = lane >> 2;
    const int lb  = tid & 63;
    const int lk0 = (tid >> 6) << 4;
    const int up  = il_row(lb);

    const float* Up = U + (long long)lb * ldu;
    const float* Wp = W + (long long)wrow * ldw;

    const int ntiles = (K + KT - 1) / KT;
    for (int t = 0; t < ntiles; ++t) {
        float ur[16], wr[16];
        load16g(ur, Up, t * KT + lk0, K);
        load16g(wr, Wp, t * KT + lk0, K);
        __syncthreads();
        #pragma unroll
        for (int j = 0; j < 16; ++j) {
            int k = lk0 + j;
            uT[k][up] = split_tf32(ur[j]);
            wT[k][(lb + 2 * (k & 3)) & 63] = split_tf32(wr[j]);
        }
        __syncthreads();
        mma_tile(acc, uT, wT, wm, wn, tig, gid);
    }
    __syncthreads();
}

// ---------- LSTM epilogue: gates -> c,h; h stored pre-split & transposed ------
__device__ __forceinline__ void lstm_epi(
    float acc[2][4][4],
    const float* __restrict__ bih, const float* __restrict__ bhh,
    float* __restrict__ cst, float2* __restrict__ hs, int u0) {
    const int tid = threadIdx.x;
    const int lane = tid & 31, w = tid >> 5, wm = w & 1, wn = w >> 1;
    const int gid = lane >> 2, q = lane & 3;
    #pragma unroll
    for (int nt = 0; nt < 4; ++nt) {
        int cA = wn * 32 + nt * 8 + 2 * q;         // even col: gate cA&3 in {0,2}
        int rA = (cA & 3) * H_ + u0 + (cA >> 2);
        int rB = ((cA + 1) & 3) * H_ + u0 + (cA >> 2);
        float bA = bih[rA] + bhh[rA];
        float bB = bih[rB] + bhh[rB];
        int unit = u0 + (cA >> 2);
        #pragma unroll
        for (int mt = 0; mt < 2; ++mt) {
            float d0 = acc[mt][nt][0] + bA;        // (row gid,   col cA)
            float d1 = acc[mt][nt][1] + bB;        // (row gid,   col cA+1)
            float d2 = acc[mt][nt][2] + bA;        // (row gid+8, col cA)
            float d3 = acc[mt][nt][3] + bB;        // (row gid+8, col cA+1)
            float o0 = __shfl_xor_sync(0xffffffffu, d0, 1);
            float o1 = __shfl_xor_sync(0xffffffffu, d1, 1);
            float o2 = __shfl_xor_sync(0xffffffffu, d2, 1);
            float o3 = __shfl_xor_sync(0xffffffffu, d3, 1);
            int row; float pi, pf, pg, po;
            if ((q & 1) == 0) {  // this lane holds (i,f); partner supplies (g,o)
                row = wm * 32 + mt * 16 + gid;
                pi = d0; pf = d1; pg = o0; po = o1;
            } else {             // this lane holds (g,o); partner supplies (i,f)
                row = wm * 32 + mt * 16 + gid + 8;
                pi = o2; pf = o3; pg = d2; po = d3;
            }
            float iv = sigf(pi), fv = sigf(pf), gv = tanhf(pg), ov = sigf(po);
            long long cidx = (long long)row * H_ + unit;
            float cn = fv * cst[cidx] + iv * gv;
            cst[cidx] = cn;
            float hv = ov * tanhf(cn);
            hs[unit * B_ + il_row(row)] = split_tf32(hv);   // pre-split for consumers
        }
    }
}

// ---------- init: zero state, barrier, out[:,0,:] -----------------------------
__global__ void init_state(float* __restrict__ out) {
    int idx = blockIdx.x * blockDim.x + threadIdx.x;
    if (idx == 0) { g_bar_count = 0; g_bar_gen = 0; }
    if (idx < 2 * H_ * B_) {
        ((float2*)g_h1s)[idx] = make_float2(0.0f, 0.0f);
        ((float2*)g_h2s)[idx] = make_float2(0.0f, 0.0f);
    }
    if (idx < B_ * H_) {
        g_c1[idx] = 0.0f;
        g_c2[idx] = 0.0f;
    }
    if (idx < B_ * O_) {
        int b = idx / O_, o = idx % O_;
        out[(long long)b * S_ * O_ + o] = 0.0f;  // t = 0 row is all zeros
    }
}

// ---------- init: pre-split weights into fragment-tile layout -----------------
__global__ void init_weights(const float* __restrict__ Whh1,
                             const float* __restrict__ Wih2,
                             const float* __restrict__ Whh2,
                             const float* __restrict__ Wout) {
    const long long PER = (long long)64 * H_ * 64;
    long long e = (long long)blockIdx.x * blockDim.x + threadIdx.x;
    if (e < 3 * PER) {
        int m = (int)(e / PER);
        long long r = e % PER;
        int cta = (int)(r / (H_ * 64));
        int rem = (int)(r % (H_ * 64));
        int k = rem / 64, col = rem % 64;
        int wrow = (col & 3) * H_ + cta * 16 + (col >> 2);
        const float* W = (m == 0) ? Whh1 : (m == 1) ? Wih2 : Whh2;
        float2 v = split_tf32(W[(long long)wrow * H_ + k]);
        int dc = (col + 2 * (k & 3)) & 63;
        if (m == 0)      g_w1h[cta][k][dc] = v;
        else if (m == 1) g_w2i[cta][k][dc] = v;
        else             g_w2h[cta][k][dc] = v;
    } else if (e < 3 * PER + (long long)2 * H_ * 64) {
        long long r = e - 3 * PER;
        int cta = (int)(r / (H_ * 64));
        int rem = (int)(r % (H_ * 64));
        int k = rem / 64, col = rem % 64;
        int wrow = cta * 64 + col;
        float val = (wrow < O_) ? Wout[(long long)wrow * H_ + k] : 0.0f;
        g_wo[cta][k][(col + 2 * (k & 3)) & 63] = split_tf32(val);
    }
}

// ---------- persistent kernel --------------------------------------------------
// One pipeline interval k per iteration (k = 0..T_+1):
//   blocks   0..63 : layer-1 -> h1(k)            (active k <= T_-1)
//   blocks  64..127: layer-2 -> h2(k-1)          (active 1 <= k <= T_)
//   blocks 128..129: output  -> out at t = k-1   (active k >= 2)
// Buffers: h1(j) lives in g_h1s[j&1]; h2(j) lives in g_h2s[j&1].
__global__ void __launch_bounds__(NTH, 1) lstm_persistent(
    const float* __restrict__ x,
    const float* __restrict__ Wih1,
    const float* __restrict__ bih1, const float* __restrict__ bhh1,
    const float* __restrict__ bih2, const float* __restrict__ bhh2,
    const float* __restrict__ bout,
    float* __restrict__ out)
{
    extern __shared__ char sm_[];
    float2 (*uS)[KT][64] = reinterpret_cast<float2 (*)[KT][64]>(sm_);
    float2 (*wS)[KT][64] = reinterpret_cast<float2 (*)[KT][64]>(sm_ + 2 * TILE_B);

    const int blk = blockIdx.x;
    const int tid = threadIdx.x;
    const int lb  = tid & 63;

    float acc[2][4][4];

    for (int k = 0; k <= T_ + 1; ++k) {
        if (blk < 64) {
            // ---- Layer 1: h1(k), c1 from h1(k-1), c1, x[:, k+1, :] ----
            if (k < T_) {
                const int u0 = blk * 16;
                #pragma unroll
                for (int a = 0; a < 2; ++a)
                    #pragma unroll
                    for (int b = 0; b < 4; ++b)
                        #pragma unroll
                        for (int c = 0; c < 4; ++c) acc[a][b][c] = 0.0f;
                const int wrow = (lb & 3) * H_ + u0 + (lb >> 2);
                gemm_x(acc, uS[0], wS[0], x + (long long)(k + 1) * I_,
                       (long long)S_ * I_, Wih1, I_, wrow, I_);
                gemm_ps(acc, uS, wS, &g_h1s[(k + 1) & 1][0][0],
                        &g_w1h[blk][0][0], H_ / KT);
                lstm_epi(acc, bih1, bhh1, g_c1, &g_h1s[k & 1][0][0], u0);
            }
        } else if (blk < 128) {
            // ---- Layer 2: h2(k-1), c2 from h1(k-1), h2(k-2), c2 ----
            if (k >= 1 && k <= T_) {
                const int cta = blk - 64;
                const int u0 = cta * 16;
                #pragma unroll
                for (int a = 0; a < 2; ++a)
                    #pragma unroll
                    for (int b = 0; b < 4; ++b)
                        #pragma unroll
                        for (int c = 0; c < 4; ++c) acc[a][b][c] = 0.0f;
                gemm_ps(acc, uS, wS, &g_h1s[(k + 1) & 1][0][0],
                        &g_w2i[cta][0][0], H_ / KT);
                gemm_ps(acc, uS, wS, &g_h2s[k & 1][0][0],
                        &g_w2h[cta][0][0], H_ / KT);
                lstm_epi(acc, bih2, bhh2, g_c2, &g_h2s[(k + 1) & 1][0][0], u0);
            }
        } else {
            // ---- Output projection: out(t'=k-2) = h2(k-2) @ Wout^T + bout ----
            if (k >= 2) {
                const int cta = blk - 128;
                const int cb = cta * 64;
                #pragma unroll
                for (int a = 0; a < 2; ++a)
                    #pragma unroll
                    for (int b = 0; b < 4; ++b)
                        #pragma unroll
                        for (int c = 0; c < 4; ++c) acc[a][b][c] = 0.0f;
                gemm_ps(acc, uS, wS, &g_h2s[k & 1][0][0],
                        &g_wo[cta][0][0], H_ / KT);

                const int lane = tid & 31, w = tid >> 5, wm = w & 1, wn = w >> 1;
                const int gid = lane >> 2, q = lane & 3;
                const int tout = k - 1;                    // out index t'+1
                #pragma unroll
                for (int nt = 0; nt < 4; ++nt) {
                    int c0 = cb + wn * 32 + nt * 8 + 2 * q;
                    #pragma unroll
                    for (int mt = 0; mt < 2; ++mt) {
                        int r0 = wm * 32 + mt * 16 + gid;
                        if (c0 < O_) {
                            float bv = bout[c0];
                            out[((long long)r0 * S_ + tout) * O_ + c0] =
                                acc[mt][nt][0] + bv;
                            out[((long long)(r0 + 8) * S_ + tout) * O_ + c0] =
                                acc[mt][nt][2] + bv;
                        }
                        if (c0 + 1 < O_) {
                            float bv = bout[c0 + 1];
                            out[((long long)r0 * S_ + tout) * O_ + c0 + 1] =
                                acc[mt][nt][1] + bv;
                            out[((long long)(r0 + 8) * S_ + tout) * O_ + c0 + 1] =
                                acc[mt][nt][3] + bv;
                        }
                    }
                }
            }
        }

        // ---- Grid barrier (all 130 CTAs resident: 130 < 148 SMs) ----
        __threadfence();     // release: this CTA's state writes visible at L2
        __syncthreads();
        if (tid == 0) {
            unsigned gen = g_bar_gen;
            unsigned t = atomicAdd(&g_bar_count, 1u);
            if (t == NBLK - 1) {
                g_bar_count = 0;
                __threadfence();
                g_bar_gen = gen + 1;
            } else {
                while (g_bar_gen == gen) { }
            }
        }
        __syncthreads();
        __threadfence();     // acquire: subsequent reads see other CTAs' writes
    }
}

extern "C" void kernel_launch(void* const* d_in, const int* in_sizes, int n_in,
                              void* d_out, int out_size) {
    const float* x    = (const float*)d_in[0];
    const float* Wih1 = (const float*)d_in[1];
    const float* Whh1 = (const float*)d_in[2];
    const float* bih1 = (const float*)d_in[3];
    const float* bhh1 = (const float*)d_in[4];
    const float* Wih2 = (const float*)d_in[5];
    const float* Whh2 = (const float*)d_in[6];
    const float* bih2 = (const float*)d_in[7];
    const float* bhh2 = (const float*)d_in[8];
    const float* Wout = (const float*)d_in[9];
    const float* bout = (const float*)d_in[10];
    float* out = (float*)d_out;

    static bool attr_done = false;
    if (!attr_done) {
        cudaFuncSetAttribute(lstm_persistent,
                             cudaFuncAttributeMaxDynamicSharedMemorySize,
                             SMEM_BYTES);
        attr_done = true;
    }

    init_state<<<512, 256>>>(out);
    {
        long long total = 3LL * 64 * H_ * 64 + 2LL * H_ * 64;
        int blocks = (int)((total + 255) / 256);
        init_weights<<<blocks, 256>>>(Whh1, Wih2, Whh2, Wout);
    }
    lstm_persistent<<<NBLK, NTH, SMEM_BYTES>>>(x, Wih1, bih1, bhh1,
                                               bih2, bhh2, bout, out);
}